// round 13
// baseline (speedup 1.0000x reference)
#include <cuda_runtime.h>

#define BATCH 16
#define IMG_H 1024
#define IMG_W 1024
#define WPR   32                 // 32-bit words per row (1024/32)
#define NROWS (BATCH * IMG_H)
#define NWORDS (NROWS * WPR)
#define NTOT  ((double)BATCH * IMG_H * IMG_W)
#define ROWS_PER_BLK 8
#define NBUCKET 32

// Scratch (allocation-free: __device__ globals). Zero-initialized at module
// load; finalize re-zeroes everything after each run (replay-deterministic).
__device__ unsigned int g_hbits[NWORDS];        // horizontal-OR (r=7) bits, 2 MB
__device__ unsigned int g_lmix[NWORDS];         // lane-remixed label bits, 2 MB
__device__ unsigned int g_bmix[NWORDS];         // lane-remixed BAND bits, 2 MB
__device__ double g_sumB[NBUCKET][3];           // bucketed sums: Not, Band, Lab
__device__ int    g_cnt[2];                     // counts: Lab, Edge
__device__ int    g_done;                       // arrival counter

// Remix layout: for row r, lane L, pixel i = 4k+j lives at image column
// 128k + 4L + j -> bit 4(L&7)+j of row-word 4k+(L>>3). mix[r*32+L] bit i is
// that pixel's bit. Consumers do ONE coalesced load, zero shuffles.

// ---------------------------------------------------------------------------
// Kernel A: 256 threads / 8 rows, front-batched streaming int4 loads.
// Produces hbits (horizontal r=7 OR) + lane-remixed label words + label count.
// ---------------------------------------------------------------------------
__global__ void __launch_bounds__(256) pack_hor(const int* __restrict__ label) {
    __shared__ unsigned int sw[ROWS_PER_BLK * WPR];
    const int t    = threadIdx.x;
    const int lane = t & 31;
    const int wid  = t >> 5;

    const int4* lab4 = (const int4*)label + (size_t)blockIdx.x * (ROWS_PER_BLK * WPR * 8);
    int4 v[8];
#pragma unroll
    for (int k = 0; k < 8; k++) v[k] = __ldcs(&lab4[k * 256 + t]);

#pragma unroll
    for (int k = 0; k < 8; k++) {
        unsigned int nib = (unsigned)v[k].x | ((unsigned)v[k].y << 1)
                         | ((unsigned)v[k].z << 2) | ((unsigned)v[k].w << 3);
        unsigned int val = nib << (4 * (lane & 7));
        val |= __shfl_xor_sync(0xffffffffu, val, 1);
        val |= __shfl_xor_sync(0xffffffffu, val, 2);
        val |= __shfl_xor_sync(0xffffffffu, val, 4);
        if ((lane & 7) == 0) sw[(k * 256 + t) >> 3] = val;
    }
    __syncthreads();

    const int w = lane;                                  // word index in row
    const int rbase = t & ~31;
    const unsigned int wl = (w > 0)       ? sw[t - 1] : 0u;
    const unsigned int wc = sw[t];
    const unsigned int wr = (w < WPR - 1) ? sw[t + 1] : 0u;
    unsigned long long a = (unsigned long long)wc | ((unsigned long long)wr << 32);
    a |= a >> 1; a |= a >> 2; a |= a >> 4;              // OR of px x..x+7
    unsigned long long c = (unsigned long long)wl | ((unsigned long long)wc << 32);
    c |= c << 1; c |= c << 2; c |= c << 4;              // OR of px x-7..x
    const size_t gidx = (size_t)blockIdx.x * (ROWS_PER_BLK * WPR) + t;
    g_hbits[gidx] = (unsigned int)a | (unsigned int)(c >> 32);

    // Lane-remix of label words via broadcast smem reads
    unsigned int lmix = 0;
    const int nsh = 4 * (w & 7);
#pragma unroll
    for (int k = 0; k < 8; k++)
        lmix |= ((sw[rbase + 4 * k + (w >> 3)] >> nsh) & 0xFu) << (4 * k);
    g_lmix[gidx] = lmix;

    int c0 = __reduce_add_sync(0xffffffffu, __popc(wc));
    __shared__ int ic[8];
    if (lane == 0) ic[wid] = c0;
    __syncthreads();
    if (t == 0) {
        int s = 0;
#pragma unroll
        for (int i = 0; i < 8; i++) s += ic[i];
        atomicAdd(&g_cnt[0], s);
    }
}

// ---------------------------------------------------------------------------
// Kernel A2: vertical r=7 OR (L2-resident) + lane-remix + band mask + edge
// count. Warp = one row (lane = word). Removes ALL mask machinery from bce.
// ---------------------------------------------------------------------------
__global__ void __launch_bounds__(256) vert_remix() {
    const int t    = threadIdx.x;
    const int lane = t & 31;
    const int wid  = t >> 5;
    const int idx  = blockIdx.x * 256 + t;              // word index
    const int row  = idx >> 5;
    const int y    = row & (IMG_H - 1);
    const int base = row - y;

    unsigned int ew = 0;
#pragma unroll
    for (int dy = -7; dy <= 7; dy++) {
        const int yy = y + dy;
        if (yy >= 0 && yy < IMG_H)
            ew |= g_hbits[(size_t)(base + yy) * WPR + lane];
    }

    // Edge count (pre-remix popc), one atomic per block
    int c0 = __reduce_add_sync(0xffffffffu, __popc(ew));
    __shared__ int ic[8];
    if (lane == 0) ic[wid] = c0;

    // Remix ew across the warp (8 independent shuffles), then band = e & ~l
    unsigned int emix = 0;
    const int nsh = 4 * (lane & 7);
#pragma unroll
    for (int k = 0; k < 8; k++)
        emix |= ((__shfl_sync(0xffffffffu, ew, 4 * k + (lane >> 3)) >> nsh) & 0xFu) << (4 * k);
    g_bmix[idx] = emix & ~g_lmix[idx];

    __syncthreads();
    if (t == 0) {
        int s = 0;
#pragma unroll
        for (int i = 0; i < 8; i++) s += ic[i];
        atomicAdd(&g_cnt[1], s);
    }
}

// ---------------------------------------------------------------------------
// Kernel B: pure BCE. Warp = one row; 8 front-batched streaming LDG.128 +
// 2 mask words. Per-chunk log-of-products (3 logs / 8 px, zero per-pixel
// MUFU): pl = prod p over label px, pn = prod (1-p) over non-label px,
// pb = prod (1-p) over band px. Last block finalizes and resets state.
// ---------------------------------------------------------------------------
__global__ void __launch_bounds__(256) bce_kernel(const float* __restrict__ Pred,
                                                  float* __restrict__ out) {
    const int t    = threadIdx.x;
    const int lane = t & 31;
    const int wid  = t >> 5;
    const int row  = blockIdx.x * 8 + wid;

    const float4* prow = (const float4*)(Pred + (size_t)row * IMG_W);
    float4 p[8];
#pragma unroll
    for (int k = 0; k < 8; k++) p[k] = __ldcs(&prow[k * 32 + lane]);
    const unsigned int mylw = g_lmix[(size_t)row * WPR + lane];
    const unsigned int mybb = g_bmix[(size_t)row * WPR + lane];

    float sNot = 0.f, sBand = 0.f, sLab = 0.f;

#define PXP(pv, mask)                                              \
    {                                                              \
        const float omp = 1.0f - (pv);                             \
        const bool tl = (mylw & (mask)) != 0u;                     \
        const bool bb = (mybb & (mask)) != 0u;                     \
        pl *= tl ? (pv) : 1.0f;                                    \
        pn *= tl ? 1.0f : omp;                                     \
        pb *= bb ? omp  : 1.0f;                                    \
    }
#pragma unroll
    for (int k = 0; k < 8; k += 2) {                     // chunk = 8 px
        float pl = 1.f, pn = 1.f, pb = 1.f;
        PXP(p[k].x,     1u << (4 * k + 0))
        PXP(p[k].y,     1u << (4 * k + 1))
        PXP(p[k].z,     1u << (4 * k + 2))
        PXP(p[k].w,     1u << (4 * k + 3))
        PXP(p[k + 1].x, 1u << (4 * k + 4))
        PXP(p[k + 1].y, 1u << (4 * k + 5))
        PXP(p[k + 1].z, 1u << (4 * k + 6))
        PXP(p[k + 1].w, 1u << (4 * k + 7))
        sLab  += __log2f(pl);
        sNot  += __log2f(pn);
        sBand += __log2f(pb);
    }
#undef PXP

#pragma unroll
    for (int off = 16; off; off >>= 1) {
        sNot  += __shfl_xor_sync(0xffffffffu, sNot,  off);
        sBand += __shfl_xor_sync(0xffffffffu, sBand, off);
        sLab  += __shfl_xor_sync(0xffffffffu, sLab,  off);
    }

    __shared__ float fs[3][8];
    if (lane == 0) { fs[0][wid] = sNot; fs[1][wid] = sBand; fs[2][wid] = sLab; }
    __syncthreads();

    __shared__ int amLast;
    if (t == 0) {
        double bN = 0, bB = 0, bL = 0;
#pragma unroll
        for (int k = 0; k < 8; k++) { bN += fs[0][k]; bB += fs[1][k]; bL += fs[2][k]; }
        const int bk = blockIdx.x & (NBUCKET - 1);      // spread atomic traffic
        atomicAdd(&g_sumB[bk][0], bN);
        atomicAdd(&g_sumB[bk][1], bB);
        atomicAdd(&g_sumB[bk][2], bL);
        __threadfence();
        amLast = (atomicAdd(&g_done, 1) == (int)gridDim.x - 1);
    }
    __syncthreads();

    if (amLast && wid == 0) {
        double n = g_sumB[lane][0];
        double b = g_sumB[lane][1];
        double l = g_sumB[lane][2];
        const int nL = g_cnt[0];
        const int nE = g_cnt[1];
#pragma unroll
        for (int off = 16; off; off >>= 1) {
            n += __shfl_xor_sync(0xffffffffu, n, off);
            b += __shfl_xor_sync(0xffffffffu, b, off);
            l += __shfl_xor_sync(0xffffffffu, l, off);
        }
        // Reset ALL accumulator state for the next graph replay
        g_sumB[lane][0] = 0.0;
        g_sumB[lane][1] = 0.0;
        g_sumB[lane][2] = 0.0;
        if (lane == 0) {
            g_cnt[0] = 0;
            g_cnt[1] = 0;
            g_done = 0;
            const double N  = NTOT;
            const double dL = (double)nL;                // label (E) count
            const double dE = (double)nE;                // edge count
            const double wE = (1.0 - dL / N) * 1.0;
            const double wB = (1.0 - (dE - dL) / N) * 0.8;
            const double wT = (1.0 - (N - dE) / N) * 0.5;
            // lg2 sums:  E = l,  B = b,  T = n - b
            const double LN2 = 0.6931471805599453;
            out[0] = (float)(-LN2 * (wE * l + wB * b + wT * (n - b)) / N);
        }
    }
}

extern "C" void kernel_launch(void* const* d_in, const int* in_sizes, int n_in,
                              void* d_out, int out_size) {
    const float* Pred  = (const float*)d_in[0];
    const int*   label = (const int*)d_in[1];
    (void)in_sizes; (void)n_in; (void)out_size;

    pack_hor<<<NROWS / ROWS_PER_BLK, 256>>>(label);
    vert_remix<<<NWORDS / 256, 256>>>();
    bce_kernel<<<NROWS / 8, 256>>>(Pred, (float*)d_out);
}

// round 14
// speedup vs baseline: 1.1803x; 1.1803x over previous
#include <cuda_runtime.h>

#define BATCH 16
#define IMG_H 1024
#define IMG_W 1024
#define WPR   32                 // 32-bit words per row (1024/32)
#define NROWS (BATCH * IMG_H)
#define NWORDS (NROWS * WPR)
#define NTOT  ((double)BATCH * IMG_H * IMG_W)
#define ROWS_PER_BLK 8
#define NBUCKET 32

// Scratch (allocation-free: __device__ globals). Zero-initialized at module
// load; finalize re-zeroes everything after each run (replay-deterministic).
__device__ unsigned int g_hbits[NWORDS];        // horizontal-OR (r=7) bits, 2 MB
__device__ unsigned int g_lmix[NWORDS];         // lane-remixed label bits, 2 MB
__device__ double g_sumB[NBUCKET][3];           // bucketed sums: Not, Band, Lab
__device__ int    g_cnt[2];                     // counts: Lab, Edge
__device__ int    g_done;                       // arrival counter

// Remix layout: for row r, lane L, pixel i = 4k+j lives at image column
// 128k + 4L + j -> bit 4(L&7)+j of row-word 4k+(L>>3). mix[r*32+L] bit i is
// that pixel's bit. Consumers do ONE coalesced load, zero shuffles.

// ---------------------------------------------------------------------------
// Kernel A: 256 threads / 8 rows, front-batched streaming int4 loads.
// Produces hbits (horizontal r=7 OR) + lane-remixed label words + label count.
// ---------------------------------------------------------------------------
__global__ void __launch_bounds__(256) pack_hor(const int* __restrict__ label) {
    __shared__ unsigned int sw[ROWS_PER_BLK * WPR];
    const int t    = threadIdx.x;
    const int lane = t & 31;
    const int wid  = t >> 5;

    const int4* lab4 = (const int4*)label + (size_t)blockIdx.x * (ROWS_PER_BLK * WPR * 8);
    int4 v[8];
#pragma unroll
    for (int k = 0; k < 8; k++) v[k] = __ldcs(&lab4[k * 256 + t]);

#pragma unroll
    for (int k = 0; k < 8; k++) {
        unsigned int nib = (unsigned)v[k].x | ((unsigned)v[k].y << 1)
                         | ((unsigned)v[k].z << 2) | ((unsigned)v[k].w << 3);
        unsigned int val = nib << (4 * (lane & 7));
        val |= __shfl_xor_sync(0xffffffffu, val, 1);
        val |= __shfl_xor_sync(0xffffffffu, val, 2);
        val |= __shfl_xor_sync(0xffffffffu, val, 4);
        if ((lane & 7) == 0) sw[(k * 256 + t) >> 3] = val;
    }
    __syncthreads();

    const int w = lane;                                  // word index in row
    const int rbase = t & ~31;
    const unsigned int wl = (w > 0)       ? sw[t - 1] : 0u;
    const unsigned int wc = sw[t];
    const unsigned int wr = (w < WPR - 1) ? sw[t + 1] : 0u;
    unsigned long long a = (unsigned long long)wc | ((unsigned long long)wr << 32);
    a |= a >> 1; a |= a >> 2; a |= a >> 4;              // OR of px x..x+7
    unsigned long long c = (unsigned long long)wl | ((unsigned long long)wc << 32);
    c |= c << 1; c |= c << 2; c |= c << 4;              // OR of px x-7..x
    const size_t gidx = (size_t)blockIdx.x * (ROWS_PER_BLK * WPR) + t;
    g_hbits[gidx] = (unsigned int)a | (unsigned int)(c >> 32);

    // Lane-remix of label words via broadcast smem reads
    unsigned int lmix = 0;
    const int nsh = 4 * (w & 7);
#pragma unroll
    for (int k = 0; k < 8; k++)
        lmix |= ((sw[rbase + 4 * k + (w >> 3)] >> nsh) & 0xFu) << (4 * k);
    g_lmix[gidx] = lmix;

    int c0 = __reduce_add_sync(0xffffffffu, __popc(wc));
    __shared__ int ic[8];
    if (lane == 0) ic[wid] = c0;
    __syncthreads();
    if (t == 0) {
        int s = 0;
#pragma unroll
        for (int i = 0; i < 8; i++) s += ic[i];
        atomicAdd(&g_cnt[0], s);
    }
}

// ---------------------------------------------------------------------------
// Kernel B: fused vertical-OR + product-BCE. Warp = one row.
// Front-batched: 8x LDG.128 Pred (streaming) + lmix + 15 coalesced L2-hot
// hbits loads. Edge remix = 8 independent shuffles; band = emix & ~lmix.
// Pixel block: 3-basis chunk products (12 MUFU/warp, no per-pixel MUFU
// chains). Last block finalizes and resets all state.
// ---------------------------------------------------------------------------
__global__ void __launch_bounds__(256) bce_kernel(const float* __restrict__ Pred,
                                                  float* __restrict__ out) {
    const int t    = threadIdx.x;
    const int lane = t & 31;
    const int wid  = t >> 5;
    const int row  = blockIdx.x * 8 + wid;
    const int y    = row & (IMG_H - 1);
    const int base = row - y;                            // image top row

    // Front-batch: Pred (DRAM) + label mix word
    const float4* prow = (const float4*)(Pred + (size_t)row * IMG_W);
    float4 p[8];
#pragma unroll
    for (int k = 0; k < 8; k++) p[k] = __ldcs(&prow[k * 32 + lane]);
    const unsigned int mylw = g_lmix[(size_t)row * WPR + lane];

    // Vertical r=7 OR straight from L2 (15 independent coalesced loads)
    unsigned int ew = 0;
#pragma unroll
    for (int dy = -7; dy <= 7; dy++) {
        const int yy = y + dy;
        if (yy >= 0 && yy < IMG_H)
            ew |= g_hbits[(size_t)(base + yy) * WPR + lane];
    }
    const int cEdge = __reduce_add_sync(0xffffffffu, __popc(ew));

    // Edge remix (8 independent shuffles); band = edge & ~label
    unsigned int emix = 0;
    const int nsh = 4 * (lane & 7);
#pragma unroll
    for (int k = 0; k < 8; k++)
        emix |= ((__shfl_sync(0xffffffffu, ew, 4 * k + (lane >> 3)) >> nsh) & 0xFu) << (4 * k);
    const unsigned int mybb = emix & ~mylw;

    // Compute: 3-basis chunk products, 3 logs per 8 pixels
    float sNot = 0.f, sBand = 0.f, sLab = 0.f;
#define PXP(pv, mask)                                              \
    {                                                              \
        const float omp = 1.0f - (pv);                             \
        const bool tl = (mylw & (mask)) != 0u;                     \
        const bool bb = (mybb & (mask)) != 0u;                     \
        pl *= tl ? (pv) : 1.0f;                                    \
        pn *= tl ? 1.0f : omp;                                     \
        pb *= bb ? omp  : 1.0f;                                    \
    }
#pragma unroll
    for (int k = 0; k < 8; k += 2) {                     // chunk = 8 px
        float pl = 1.f, pn = 1.f, pb = 1.f;
        PXP(p[k].x,     1u << (4 * k + 0))
        PXP(p[k].y,     1u << (4 * k + 1))
        PXP(p[k].z,     1u << (4 * k + 2))
        PXP(p[k].w,     1u << (4 * k + 3))
        PXP(p[k + 1].x, 1u << (4 * k + 4))
        PXP(p[k + 1].y, 1u << (4 * k + 5))
        PXP(p[k + 1].z, 1u << (4 * k + 6))
        PXP(p[k + 1].w, 1u << (4 * k + 7))
        sLab  += __log2f(pl);
        sNot  += __log2f(pn);
        sBand += __log2f(pb);
    }
#undef PXP

#pragma unroll
    for (int off = 16; off; off >>= 1) {
        sNot  += __shfl_xor_sync(0xffffffffu, sNot,  off);
        sBand += __shfl_xor_sync(0xffffffffu, sBand, off);
        sLab  += __shfl_xor_sync(0xffffffffu, sLab,  off);
    }

    __shared__ float fs[3][8];
    __shared__ int   ie[8];
    if (lane == 0) {
        fs[0][wid] = sNot; fs[1][wid] = sBand; fs[2][wid] = sLab;
        ie[wid] = cEdge;
    }
    __syncthreads();

    __shared__ int amLast;
    if (t == 0) {
        double bN = 0, bB = 0, bL = 0; int iE = 0;
#pragma unroll
        for (int k = 0; k < 8; k++) {
            bN += fs[0][k]; bB += fs[1][k]; bL += fs[2][k]; iE += ie[k];
        }
        const int bk = blockIdx.x & (NBUCKET - 1);      // spread atomic traffic
        atomicAdd(&g_sumB[bk][0], bN);
        atomicAdd(&g_sumB[bk][1], bB);
        atomicAdd(&g_sumB[bk][2], bL);
        atomicAdd(&g_cnt[1], iE);
        __threadfence();
        amLast = (atomicAdd(&g_done, 1) == (int)gridDim.x - 1);
    }
    __syncthreads();

    if (amLast && wid == 0) {
        double n = g_sumB[lane][0];
        double b = g_sumB[lane][1];
        double l = g_sumB[lane][2];
        const int nL = g_cnt[0];
        const int nE = g_cnt[1];
#pragma unroll
        for (int off = 16; off; off >>= 1) {
            n += __shfl_xor_sync(0xffffffffu, n, off);
            b += __shfl_xor_sync(0xffffffffu, b, off);
            l += __shfl_xor_sync(0xffffffffu, l, off);
        }
        // Reset ALL accumulator state for the next graph replay
        g_sumB[lane][0] = 0.0;
        g_sumB[lane][1] = 0.0;
        g_sumB[lane][2] = 0.0;
        if (lane == 0) {
            g_cnt[0] = 0;
            g_cnt[1] = 0;
            g_done = 0;
            const double N  = NTOT;
            const double dL = (double)nL;                // label (E) count
            const double dE = (double)nE;                // edge count
            const double wE = (1.0 - dL / N) * 1.0;
            const double wB = (1.0 - (dE - dL) / N) * 0.8;
            const double wT = (1.0 - (N - dE) / N) * 0.5;
            // lg2 sums:  E = l,  B = b,  T = n - b
            const double LN2 = 0.6931471805599453;
            out[0] = (float)(-LN2 * (wE * l + wB * b + wT * (n - b)) / N);
        }
    }
}

extern "C" void kernel_launch(void* const* d_in, const int* in_sizes, int n_in,
                              void* d_out, int out_size) {
    const float* Pred  = (const float*)d_in[0];
    const int*   label = (const int*)d_in[1];
    (void)in_sizes; (void)n_in; (void)out_size;

    pack_hor<<<NROWS / ROWS_PER_BLK, 256>>>(label);
    bce_kernel<<<NROWS / 8, 256>>>(Pred, (float*)d_out);
}